// round 8
// baseline (speedup 1.0000x reference)
#include <cuda_runtime.h>
#include <cstdint>

// ---------------- Problem constants ----------------
#define NMAX    50000
#define EMAX    800000
#define ETOTMAX (EMAX + NMAX)
#define GG      64
#define INC     128
#define HIDC    64
#define NHEADS  4
#define F1      (NHEADS * HIDC)   // 256
#define OUTC    10
#define NEG     0.2f
#define EPSV    1e-16f
#define FLTMAX  3.402823466e38f

// ---------------- Device scratch ----------------
__device__ float d_h[(size_t)NMAX * F1];
__device__ float d_feat[(size_t)NMAX * F1];
__device__ __align__(16) float d_asrcA[NMAX * NHEADS];
__device__ __align__(16) float d_adstA[NMAX * NHEADS];
__device__ __align__(16) float d_asrcB[NMAX * NHEADS];
__device__ __align__(16) float d_adstB[NMAX * NHEADS];
__device__ int   d_deg[NMAX];
__device__ int   d_off[NMAX];
__device__ int   d_cur[NMAX];
__device__ int   d_bsum[64];
__device__ int   d_csr_src[ETOTMAX];
__device__ float d_pool[GG * HIDC];
__device__ float d_cnt[GG];
// tf32-pre-rounded weights (ONLY referenced from device code)
__device__ float d_W1t[INC * F1];
__device__ float d_W2t[F1 * F1];
__device__ float d_W3t[F1 * HIDC];
// precomputed W @ a vectors, PERMUTED for conflict-free LDS
__device__ float4 d_wa1s[INC], d_wa1d[INC];
__device__ float4 d_wa2s[F1],  d_wa2d[F1];
__device__ float  d_wa3s[F1],  d_wa3d[F1];

__device__ __forceinline__ uint32_t cvt_tf32(float x) {
    uint32_t u;
    asm("cvt.rna.tf32.f32 %0, %1;" : "=r"(u) : "f"(x));
    return u;
}

// ================= weight rounding: W -> tf32 bit patterns =================
__global__ void round_w(const float* __restrict__ W1, const float* __restrict__ W2,
                        const float* __restrict__ W3) {
    int i = blockIdx.x * 256 + threadIdx.x;
    if (i < INC * F1) d_W1t[i] = __uint_as_float(cvt_tf32(W1[i]));
    if (i < F1 * F1)  d_W2t[i] = __uint_as_float(cvt_tf32(W2[i]));
    if (i < F1 * HIDC) d_W3t[i] = __uint_as_float(cvt_tf32(W3[i]));
}

// ================= wa precompute =================
__global__ void wa_prep(const float* __restrict__ W1, const float* __restrict__ as1, const float* __restrict__ ad1,
                        const float* __restrict__ W2, const float* __restrict__ as2, const float* __restrict__ ad2,
                        const float* __restrict__ W3, const float* __restrict__ as3, const float* __restrict__ ad3) {
    int k = blockIdx.x * 256 + threadIdx.x;
    if (k < INC) {
        float4 s, d;
        float* sp = (float*)&s; float* dp = (float*)&d;
#pragma unroll
        for (int h = 0; h < NHEADS; h++) {
            float ss = 0.f, dd = 0.f;
#pragma unroll
            for (int c = 0; c < HIDC; c++) {
                float w = W1[(size_t)k * F1 + h * HIDC + c];
                ss += w * as1[h * HIDC + c];
                dd += w * ad1[h * HIDC + c];
            }
            sp[h] = ss; dp[h] = dd;
        }
        int p = (k & 3) * 32 + (k >> 2);
        d_wa1s[p] = s; d_wa1d[p] = d;
    }
    if (k < F1) {
        float4 s, d;
        float* sp = (float*)&s; float* dp = (float*)&d;
#pragma unroll
        for (int h = 0; h < NHEADS; h++) {
            float ss = 0.f, dd = 0.f;
#pragma unroll
            for (int c = 0; c < HIDC; c++) {
                float w = W2[(size_t)k * F1 + h * HIDC + c];
                ss += w * as2[h * HIDC + c];
                dd += w * ad2[h * HIDC + c];
            }
            sp[h] = ss; dp[h] = dd;
        }
        int p = (k & 7) * 32 + (k >> 3);
        d_wa2s[p] = s; d_wa2d[p] = d;

        float s3 = 0.f, d3 = 0.f;
#pragma unroll
        for (int c = 0; c < HIDC; c++) {
            float w = W3[(size_t)k * HIDC + c];
            s3 += w * as3[c];
            d3 += w * ad3[c];
        }
        d_wa3s[p] = s3; d_wa3d[p] = d3;
    }
}

// ================= zero: deg/cur/pool/cnt =================
__global__ void zero_all(int n) {
    int i = blockIdx.x * blockDim.x + threadIdx.x;
    if (i < n) { d_deg[i] = 0; d_cur[i] = 0; }
    if (i < GG * HIDC) d_pool[i] = 0.f;
    if (i < GG) d_cnt[i] = 0.f;
}

// ================= CSR construction =================
__global__ void hist_k(const int* __restrict__ ei, int E, int n) {
    int e = blockIdx.x * blockDim.x + threadIdx.x;
    int Etot = E + n;
    if (e >= Etot) return;
    int d = (e < E) ? __ldg(&ei[E + e]) : (e - E);
    atomicAdd(&d_deg[d], 1);
}

__global__ void scan_blk(int n) {
    int i = blockIdx.x * 1024 + threadIdx.x;
    int lane = threadIdx.x & 31, wid = threadIdx.x >> 5;
    int v = (i < n) ? d_deg[i] : 0;
    int x = v;
#pragma unroll
    for (int o = 1; o < 32; o <<= 1) {
        int t = __shfl_up_sync(0xffffffffu, x, o);
        if (lane >= o) x += t;
    }
    __shared__ int ws[32];
    if (lane == 31) ws[wid] = x;
    __syncthreads();
    if (wid == 0) {
        int y = ws[lane];
#pragma unroll
        for (int o = 1; o < 32; o <<= 1) {
            int t = __shfl_up_sync(0xffffffffu, y, o);
            if (lane >= o) y += t;
        }
        ws[lane] = y;
    }
    __syncthreads();
    int incl = x + (wid ? ws[wid - 1] : 0);
    if (i < n) d_off[i] = incl - v;
    if (threadIdx.x == 1023) d_bsum[blockIdx.x] = incl;
}

__global__ void scan_top(int nb) {
    int tid = threadIdx.x;
    int lane = tid & 31, wid = tid >> 5;
    int v = (tid < nb) ? d_bsum[tid] : 0;
    int x = v;
#pragma unroll
    for (int o = 1; o < 32; o <<= 1) {
        int t = __shfl_up_sync(0xffffffffu, x, o);
        if (lane >= o) x += t;
    }
    __shared__ int w0;
    if (wid == 0 && lane == 31) w0 = x;
    __syncthreads();
    int incl = x + (wid ? w0 : 0);
    if (tid < nb) d_bsum[tid] = incl - v;
}

__global__ void scan_add(int n) {
    int i = blockIdx.x * 1024 + threadIdx.x;
    if (i < n) d_off[i] += d_bsum[blockIdx.x];
}

__global__ void scatter_k(const int* __restrict__ ei, int E, int n) {
    int e = blockIdx.x * blockDim.x + threadIdx.x;
    int Etot = E + n;
    if (e >= Etot) return;
    int s, d;
    if (e < E) { s = __ldg(&ei[e]); d = __ldg(&ei[E + e]); } else { s = d = e - E; }
    int pos = d_off[d] + atomicAdd(&d_cur[d], 1);
    d_csr_src[pos] = s;
}

// ================= layer-1 attention coefficients =================
__global__ void gemv_attn(const float* __restrict__ x, int n) {
    __shared__ float4 ws[INC], wd[INC];
    for (int i = threadIdx.x; i < INC; i += 256) { ws[i] = d_wa1s[i]; wd[i] = d_wa1d[i]; }
    __syncthreads();
    int warp = (blockIdx.x * blockDim.x + threadIdx.x) >> 5;
    int lane = threadIdx.x & 31;
    if (warp >= n) return;
    float4 xv = *reinterpret_cast<const float4*>(&x[(size_t)warp * INC + lane * 4]);
    float xr[4] = {xv.x, xv.y, xv.z, xv.w};
    float ps[NHEADS] = {}, pd[NHEADS] = {};
#pragma unroll
    for (int j = 0; j < 4; j++) {
        float4 a = ws[j * 32 + lane];
        float4 b = wd[j * 32 + lane];
        ps[0] = fmaf(xr[j], a.x, ps[0]); ps[1] = fmaf(xr[j], a.y, ps[1]);
        ps[2] = fmaf(xr[j], a.z, ps[2]); ps[3] = fmaf(xr[j], a.w, ps[3]);
        pd[0] = fmaf(xr[j], b.x, pd[0]); pd[1] = fmaf(xr[j], b.y, pd[1]);
        pd[2] = fmaf(xr[j], b.z, pd[2]); pd[3] = fmaf(xr[j], b.w, pd[3]);
    }
#pragma unroll
    for (int h = 0; h < NHEADS; h++) {
#pragma unroll
        for (int o = 16; o; o >>= 1) {
            ps[h] += __shfl_xor_sync(0xffffffffu, ps[h], o);
            pd[h] += __shfl_xor_sync(0xffffffffu, pd[h], o);
        }
    }
    if (!lane) {
#pragma unroll
        for (int h = 0; h < NHEADS; h++) {
            d_asrcA[warp * NHEADS + h] = ps[h];
            d_adstA[warp * NHEADS + h] = pd[h];
        }
    }
}

// ================= TF32 GEMM: no mainloop cvt =================
__device__ __forceinline__ void mma_tf32(float c[4], uint32_t a0, uint32_t a1,
                                         uint32_t a2, uint32_t a3,
                                         uint32_t b0, uint32_t b1) {
    asm volatile(
        "mma.sync.aligned.m16n8k8.row.col.f32.tf32.tf32.f32 "
        "{%0,%1,%2,%3}, {%4,%5,%6,%7}, {%8,%9}, {%0,%1,%2,%3};"
        : "+f"(c[0]), "+f"(c[1]), "+f"(c[2]), "+f"(c[3])
        : "r"(a0), "r"(a1), "r"(a2), "r"(a3), "r"(b0), "r"(b1));
}

__device__ __forceinline__ void cp16(void* smem_dst, const void* gsrc) {
    unsigned sa = (unsigned)__cvta_generic_to_shared(smem_dst);
    asm volatile("cp.async.ca.shared.global [%0], [%1], 16;\n" :: "r"(sa), "l"(gsrc));
}
__device__ __forceinline__ void cp_commit() { asm volatile("cp.async.commit_group;"); }
template <int N>
__device__ __forceinline__ void cp_wait() { asm volatile("cp.async.wait_group %0;" :: "n"(N)); }

// d_h[M,NOUT] = A[M,K] @ Wt[K,NOUT]; WSEL selects pre-rounded weight (device symbol).
template <int K, int NOUT, bool AG, int BN, int WM, int WN, int WSEL>
__launch_bounds__(256, 2)
__global__ void tgemm_k(const float* __restrict__ Ain, int M) {
    constexpr int BM = 128, BK = 16;
    constexpr int MT = BM / (WM * 16);
    constexpr int NT = BN / (WN * 8);
    __shared__ uint32_t As[2][BK][BM + 8];   // k-major tf32 bits
    __shared__ uint32_t Bs[2][BK][BN + 8];   // k-major tf32 bits via cp.async
    const float* A  = AG ? (const float*)d_feat : Ain;
    const float* Bt = (WSEL == 1) ? (const float*)d_W1t
                    : (WSEL == 2) ? (const float*)d_W2t
                                  : (const float*)d_W3t;

    int tid = threadIdx.x;
    int wid = tid >> 5, lane = tid & 31;
    int wm = wid % WM, wn = wid / WM;
    int row0 = blockIdx.y * BM;
    int col0 = blockIdx.x * BN;
    int lr = lane >> 2, lc = lane & 3;

    float c[MT][NT][4];
#pragma unroll
    for (int i = 0; i < MT; i++)
#pragma unroll
        for (int j = 0; j < NT; j++)
#pragma unroll
            for (int q = 0; q < 4; q++) c[i][j][q] = 0.f;

    constexpr int B4 = BN / 4;
    constexpr int BLD = (BK * B4) / 256;
    const int nk = K / BK;

    float4 areg[2];

    // prologue
    {
#pragma unroll
        for (int j = 0; j < 2; j++) {
            int idx = tid + j * 256;
            int r = idx >> 2, q = idx & 3;
            areg[j] = make_float4(0.f, 0.f, 0.f, 0.f);
            if (row0 + r < M)
                areg[j] = *reinterpret_cast<const float4*>(&A[(size_t)(row0 + r) * K + q * 4]);
        }
#pragma unroll
        for (int j = 0; j < BLD; j++) {
            int idx = tid + j * 256;
            int r = idx / B4, q = idx % B4;
            cp16(&Bs[0][r][q * 4], &Bt[(size_t)r * NOUT + col0 + q * 4]);
        }
        cp_commit();
#pragma unroll
        for (int j = 0; j < 2; j++) {
            int idx = tid + j * 256;
            int r = idx >> 2, q = idx & 3;
            As[0][q * 4 + 0][r] = cvt_tf32(areg[j].x);
            As[0][q * 4 + 1][r] = cvt_tf32(areg[j].y);
            As[0][q * 4 + 2][r] = cvt_tf32(areg[j].z);
            As[0][q * 4 + 3][r] = cvt_tf32(areg[j].w);
        }
    }

    for (int t = 0; t < nk; t++) {
        int cur = t & 1;
        if (t + 1 < nk) {
            int k0 = (t + 1) * BK;
#pragma unroll
            for (int j = 0; j < 2; j++) {
                int idx = tid + j * 256;
                int r = idx >> 2, q = idx & 3;
                areg[j] = make_float4(0.f, 0.f, 0.f, 0.f);
                if (row0 + r < M)
                    areg[j] = *reinterpret_cast<const float4*>(&A[(size_t)(row0 + r) * K + k0 + q * 4]);
            }
#pragma unroll
            for (int j = 0; j < BLD; j++) {
                int idx = tid + j * 256;
                int r = idx / B4, q = idx % B4;
                cp16(&Bs[1 - cur][r][q * 4], &Bt[(size_t)(k0 + r) * NOUT + col0 + q * 4]);
            }
            cp_commit();
            cp_wait<1>();
        } else {
            cp_wait<0>();
        }
        __syncthreads();

#pragma unroll
        for (int kk = 0; kk < BK; kk += 8) {
            uint32_t af[MT][4], bf[NT][2];
#pragma unroll
            for (int mt = 0; mt < MT; mt++) {
                int bm = wm * MT * 16 + mt * 16;
                af[mt][0] = As[cur][kk + lc][bm + lr];
                af[mt][1] = As[cur][kk + lc][bm + lr + 8];
                af[mt][2] = As[cur][kk + lc + 4][bm + lr];
                af[mt][3] = As[cur][kk + lc + 4][bm + lr + 8];
            }
#pragma unroll
            for (int nt = 0; nt < NT; nt++) {
                int bn = wn * NT * 8 + nt * 8;
                bf[nt][0] = Bs[cur][kk + lc][bn + lr];
                bf[nt][1] = Bs[cur][kk + lc + 4][bn + lr];
            }
#pragma unroll
            for (int mt = 0; mt < MT; mt++)
#pragma unroll
                for (int nt = 0; nt < NT; nt++)
                    mma_tf32(c[mt][nt], af[mt][0], af[mt][1], af[mt][2], af[mt][3],
                             bf[nt][0], bf[nt][1]);
        }

        if (t + 1 < nk) {
#pragma unroll
            for (int j = 0; j < 2; j++) {
                int idx = tid + j * 256;
                int r = idx >> 2, q = idx & 3;
                As[1 - cur][q * 4 + 0][r] = cvt_tf32(areg[j].x);
                As[1 - cur][q * 4 + 1][r] = cvt_tf32(areg[j].y);
                As[1 - cur][q * 4 + 2][r] = cvt_tf32(areg[j].z);
                As[1 - cur][q * 4 + 3][r] = cvt_tf32(areg[j].w);
            }
        }
        __syncthreads();
    }

#pragma unroll
    for (int mt = 0; mt < MT; mt++) {
        int r0 = row0 + wm * MT * 16 + mt * 16 + lr;
#pragma unroll
        for (int nt = 0; nt < NT; nt++) {
            int cc = col0 + wn * NT * 8 + nt * 8 + 2 * lc;
            if (r0 < M)
                *reinterpret_cast<float2*>(&d_h[(size_t)r0 * NOUT + cc]) =
                    make_float2(c[mt][nt][0], c[mt][nt][1]);
            if (r0 + 8 < M)
                *reinterpret_cast<float2*>(&d_h[(size_t)(r0 + 8) * NOUT + cc]) =
                    make_float2(c[mt][nt][2], c[mt][nt][3]);
        }
    }
}

// ================= fused aggregation (warp per dst node) =================
template <int H, int HN, bool DOELU, bool SRCA, bool POOL>
__launch_bounds__(256)
__global__ void agg_k(const float* __restrict__ bias, const int* __restrict__ batch, int n) {
    constexpr int C = 64, F = H * C, RF = F / 32;
    __shared__ float4 wsn4[HN == 4 ? F : 1], wdn4[HN == 4 ? F : 1];
    __shared__ float  wsn1[HN == 1 ? F : 1], wdn1[HN == 1 ? F : 1];
    if (HN == 4) {
        for (int i = threadIdx.x; i < F; i += 256) { wsn4[i] = d_wa2s[i]; wdn4[i] = d_wa2d[i]; }
        __syncthreads();
    } else if (HN == 1) {
        for (int i = threadIdx.x; i < F; i += 256) { wsn1[i] = d_wa3s[i]; wdn1[i] = d_wa3d[i]; }
        __syncthreads();
    }
    const float* asrc  = SRCA ? d_asrcA : d_asrcB;
    const float* adstp = SRCA ? d_adstA : d_adstB;
    float* nsrc = SRCA ? d_asrcB : d_asrcA;
    float* ndst = SRCA ? d_adstB : d_adstA;

    int warp = (blockIdx.x * blockDim.x + threadIdx.x) >> 5;
    int lane = threadIdx.x & 31;
    if (warp >= n) return;
    int dn = warp;
    int off = d_off[dn], deg = d_deg[dn];

    float ad[H];
#pragma unroll
    for (int h = 0; h < H; h++) ad[h] = adstp[dn * H + h];

    float mx[H], sv[H];
#pragma unroll
    for (int h = 0; h < H; h++) { mx[h] = -FLTMAX; sv[h] = 0.f; }
    for (int j = lane; j < deg; j += 32) {
        int s = d_csr_src[off + j];
        float av[H];
        if (H == 4) {
            float4 a4 = *reinterpret_cast<const float4*>(&asrc[s * 4]);
            av[0] = a4.x; av[1] = a4.y; av[2] = a4.z; av[3] = a4.w;
        } else {
            av[0] = asrc[s];
        }
#pragma unroll
        for (int h = 0; h < H; h++) {
            float v = av[h] + ad[h];
            v = v > 0.f ? v : NEG * v;
            float nm = fmaxf(mx[h], v);
            sv[h] = sv[h] * __expf(mx[h] - nm) + __expf(v - nm);
            mx[h] = nm;
        }
    }
#pragma unroll
    for (int h = 0; h < H; h++) {
#pragma unroll
        for (int o = 16; o; o >>= 1) {
            float om = __shfl_xor_sync(0xffffffffu, mx[h], o);
            float os = __shfl_xor_sync(0xffffffffu, sv[h], o);
            float nm = fmaxf(mx[h], om);
            sv[h] = sv[h] * __expf(mx[h] - nm) + os * __expf(om - nm);
            mx[h] = nm;
        }
        sv[h] = 1.f / (sv[h] + EPSV);
    }

    const int head = (H == 4) ? (lane >> 3) : 0;
    float acc[RF];
#pragma unroll
    for (int k = 0; k < RF; k++) acc[k] = 0.f;

#pragma unroll 2
    for (int j = 0; j < deg; j++) {
        int s = d_csr_src[off + j];
        float v = asrc[s * H + head] + ad[head];
        v = v > 0.f ? v : NEG * v;
        float w = __expf(v - mx[head]) * sv[head];
        const float* hs = &d_h[(size_t)s * F + lane * RF];
        if (RF == 8) {
            float4 v0 = *reinterpret_cast<const float4*>(hs);
            float4 v1 = *reinterpret_cast<const float4*>(hs + 4);
            acc[0] = fmaf(w, v0.x, acc[0]); acc[1] = fmaf(w, v0.y, acc[1]);
            acc[2] = fmaf(w, v0.z, acc[2]); acc[3] = fmaf(w, v0.w, acc[3]);
            acc[4] = fmaf(w, v1.x, acc[4]); acc[5] = fmaf(w, v1.y, acc[5]);
            acc[6] = fmaf(w, v1.z, acc[6]); acc[7] = fmaf(w, v1.w, acc[7]);
        } else {
            float2 v0 = *reinterpret_cast<const float2*>(hs);
            acc[0] = fmaf(w, v0.x, acc[0]); acc[1] = fmaf(w, v0.y, acc[1]);
        }
    }

#pragma unroll
    for (int k = 0; k < RF; k++) {
        float v = acc[k] + bias[lane * RF + k];
        if (DOELU) v = v > 0.f ? v : (__expf(v) - 1.f);
        acc[k] = v;
    }

    if (POOL) {
        int g = __ldg(&batch[dn]);
        atomicAdd(&d_pool[g * HIDC + lane * RF + 0], acc[0]);
        atomicAdd(&d_pool[g * HIDC + lane * RF + 1], acc[1]);
        if (!lane) atomicAdd(&d_cnt[g], 1.0f);
    } else {
        float* outp = &d_feat[(size_t)dn * F + lane * RF];
        if (RF == 8) {
            *reinterpret_cast<float4*>(outp)     = make_float4(acc[0], acc[1], acc[2], acc[3]);
            *reinterpret_cast<float4*>(outp + 4) = make_float4(acc[4], acc[5], acc[6], acc[7]);
        } else {
            *reinterpret_cast<float2*>(outp) = make_float2(acc[0], acc[1]);
        }
    }

    if (HN == 4) {
        float ps[4] = {}, pd[4] = {};
#pragma unroll
        for (int k = 0; k < RF; k++) {
            float4 a = wsn4[k * 32 + lane];
            float4 b = wdn4[k * 32 + lane];
            ps[0] = fmaf(acc[k], a.x, ps[0]); ps[1] = fmaf(acc[k], a.y, ps[1]);
            ps[2] = fmaf(acc[k], a.z, ps[2]); ps[3] = fmaf(acc[k], a.w, ps[3]);
            pd[0] = fmaf(acc[k], b.x, pd[0]); pd[1] = fmaf(acc[k], b.y, pd[1]);
            pd[2] = fmaf(acc[k], b.z, pd[2]); pd[3] = fmaf(acc[k], b.w, pd[3]);
        }
#pragma unroll
        for (int h = 0; h < 4; h++) {
#pragma unroll
            for (int o = 16; o; o >>= 1) {
                ps[h] += __shfl_xor_sync(0xffffffffu, ps[h], o);
                pd[h] += __shfl_xor_sync(0xffffffffu, pd[h], o);
            }
        }
        if (!lane) {
#pragma unroll
            for (int h = 0; h < 4; h++) {
                nsrc[dn * 4 + h] = ps[h];
                ndst[dn * 4 + h] = pd[h];
            }
        }
    } else if (HN == 1) {
        float ps = 0.f, pd = 0.f;
#pragma unroll
        for (int k = 0; k < RF; k++) {
            ps = fmaf(acc[k], wsn1[k * 32 + lane], ps);
            pd = fmaf(acc[k], wdn1[k * 32 + lane], pd);
        }
#pragma unroll
        for (int o = 16; o; o >>= 1) {
            ps += __shfl_xor_sync(0xffffffffu, ps, o);
            pd += __shfl_xor_sync(0xffffffffu, pd, o);
        }
        if (!lane) { nsrc[dn] = ps; ndst[dn] = pd; }
    }
}

// ---------------- head ----------------
__global__ void head_k(const float* __restrict__ Wc, const float* __restrict__ bc,
                       float* __restrict__ out) {
    int t = blockIdx.x * blockDim.x + threadIdx.x;
    if (t >= GG * OUTC) return;
    int g = t / OUTC, o = t % OUTC;
    float inv = 1.f / fmaxf(d_cnt[g], 1.f);
    float s = 0.f;
#pragma unroll
    for (int c = 0; c < HIDC; c++) s += d_pool[g * HIDC + c] * Wc[c * OUTC + o];
    out[t] = s * inv + bc[o];
}

// ---------------- host orchestration ----------------
extern "C" void kernel_launch(void* const* d_in, const int* in_sizes, int n_in,
                              void* d_out, int out_size) {
    const float* x   = (const float*)d_in[0];
    const int*   ei  = (const int*)d_in[1];
    const int*   bat = (const int*)d_in[2];
    const float* W1 = (const float*)d_in[3],  *as1 = (const float*)d_in[4],
               * ad1 = (const float*)d_in[5], *b1  = (const float*)d_in[6];
    const float* W2 = (const float*)d_in[7],  *as2 = (const float*)d_in[8],
               * ad2 = (const float*)d_in[9], *b2  = (const float*)d_in[10];
    const float* W3 = (const float*)d_in[11], *as3 = (const float*)d_in[12],
               * ad3 = (const float*)d_in[13],*b3  = (const float*)d_in[14];
    const float* Wc = (const float*)d_in[15], *bc  = (const float*)d_in[16];
    float* out = (float*)d_out;

    int n    = in_sizes[0] / INC;
    int E    = in_sizes[1] / 2;
    int Etot = E + n;

    int gemm_rows = (n + 127) / 128;
    int eb   = (Etot + 255) / 256;
    int nb   = (n + 255) / 256;
    int sb   = (n + 1023) / 1024;
    int aggb = (n * 32 + 255) / 256;

    // launch index 3 gets ncu-profiled -> layer-1 GEMM there
    wa_prep<<<1, 256>>>(W1, as1, ad1, W2, as2, ad2, W3, as3, ad3);          // 0
    round_w<<<(F1 * F1 + 255) / 256, 256>>>(W1, W2, W3);                    // 1
    zero_all<<<nb, 256>>>(n);                                               // 2
    tgemm_k<INC, F1, false, 128, 2, 4, 1><<<dim3(F1 / 128, gemm_rows), 256>>>(x, n); // 3
    hist_k<<<eb, 256>>>(ei, E, n);                                          // 4
    scan_blk<<<sb, 1024>>>(n);                                              // 5
    scan_top<<<1, 64>>>(sb);                                                // 6
    scan_add<<<sb, 1024>>>(n);                                              // 7
    scatter_k<<<eb, 256>>>(ei, E, n);                                       // 8
    gemv_attn<<<(n + 7) / 8, 256>>>(x, n);                                  // 9

    // ---- Layer 1 agg (heads=4); writes layer-2 coeffs ----
    agg_k<NHEADS, NHEADS, true, true, false><<<aggb, 256>>>(b1, nullptr, n);

    // ---- Layer 2 (heads=4, in=256, out=256) ----
    tgemm_k<F1, F1, true, 128, 2, 4, 2><<<dim3(F1 / 128, gemm_rows), 256>>>(nullptr, n);
    agg_k<NHEADS, 1, true, false, false><<<aggb, 256>>>(b2, nullptr, n);

    // ---- Layer 3 (heads=1, in=256, out=64) ----
    tgemm_k<F1, HIDC, true, 64, 4, 2, 3><<<dim3(1, gemm_rows), 256>>>(nullptr, n);
    agg_k<1, 0, false, true, true><<<aggb, 256>>>(b3, bat, n);

    // ---- head ----
    head_k<<<(GG * OUTC + 255) / 256, 256>>>(Wc, bc, out);
}

// round 9
// speedup vs baseline: 1.1759x; 1.1759x over previous
#include <cuda_runtime.h>
#include <cstdint>

// ---------------- Problem constants ----------------
#define NMAX    50000
#define EMAX    800000
#define ETOTMAX (EMAX + NMAX)
#define GG      64
#define INC     128
#define HIDC    64
#define NHEADS  4
#define F1      (NHEADS * HIDC)   // 256
#define OUTC    10
#define NEG     0.2f
#define EPSV    1e-16f
#define FLTMAX  3.402823466e38f

// ---------------- Device scratch ----------------
__device__ float d_h[(size_t)NMAX * F1];
__device__ float d_feat[(size_t)NMAX * F1];
__device__ __align__(16) float d_asrcA[NMAX * NHEADS];
__device__ __align__(16) float d_adstA[NMAX * NHEADS];
__device__ __align__(16) float d_asrcB[NMAX * NHEADS];
__device__ __align__(16) float d_adstB[NMAX * NHEADS];
__device__ int   d_deg[NMAX];
__device__ int   d_off[NMAX];
__device__ int   d_cur[NMAX];
__device__ int   d_bsum[64];
__device__ int   d_csr_src[ETOTMAX];
__device__ float d_pool[GG * HIDC];
__device__ float d_cnt[GG];
// precomputed W @ a vectors, PERMUTED: p(ch) = (ch>>7)*128 + (ch&3)*32 + ((ch>>2)&31)
__device__ float4 d_wa1s[INC], d_wa1d[INC];
__device__ float4 d_wa2s[F1],  d_wa2d[F1];
__device__ float  d_wa3s[F1],  d_wa3d[F1];

__device__ __forceinline__ int waperm(int ch) {
    return (ch >> 7) * 128 + (ch & 3) * 32 + ((ch >> 2) & 31);
}

// ================= wa precompute: warp per k, coalesced =================
__global__ void wa_prep(const float* __restrict__ W1, const float* __restrict__ as1, const float* __restrict__ ad1,
                        const float* __restrict__ W2, const float* __restrict__ as2, const float* __restrict__ ad2,
                        const float* __restrict__ W3, const float* __restrict__ as3, const float* __restrict__ ad3) {
    int gw = (blockIdx.x * blockDim.x + threadIdx.x) >> 5;   // 0..255
    int lane = threadIdx.x & 31;
    if (gw >= F1) return;
    int k = gw;

    if (k < INC) {  // W1 row
        float4 s, d;
        float* sp = (float*)&s; float* dp = (float*)&d;
#pragma unroll
        for (int h = 0; h < NHEADS; h++) {
            float w0 = W1[(size_t)k * F1 + h * HIDC + lane];
            float w1 = W1[(size_t)k * F1 + h * HIDC + lane + 32];
            float ss = w0 * as1[h * HIDC + lane] + w1 * as1[h * HIDC + lane + 32];
            float dd = w0 * ad1[h * HIDC + lane] + w1 * ad1[h * HIDC + lane + 32];
#pragma unroll
            for (int o = 16; o; o >>= 1) {
                ss += __shfl_xor_sync(0xffffffffu, ss, o);
                dd += __shfl_xor_sync(0xffffffffu, dd, o);
            }
            sp[h] = ss; dp[h] = dd;
        }
        if (!lane) { int p = waperm(k); d_wa1s[p] = s; d_wa1d[p] = d; }
    }
    {   // W2 row
        float4 s, d;
        float* sp = (float*)&s; float* dp = (float*)&d;
#pragma unroll
        for (int h = 0; h < NHEADS; h++) {
            float w0 = W2[(size_t)k * F1 + h * HIDC + lane];
            float w1 = W2[(size_t)k * F1 + h * HIDC + lane + 32];
            float ss = w0 * as2[h * HIDC + lane] + w1 * as2[h * HIDC + lane + 32];
            float dd = w0 * ad2[h * HIDC + lane] + w1 * ad2[h * HIDC + lane + 32];
#pragma unroll
            for (int o = 16; o; o >>= 1) {
                ss += __shfl_xor_sync(0xffffffffu, ss, o);
                dd += __shfl_xor_sync(0xffffffffu, dd, o);
            }
            sp[h] = ss; dp[h] = dd;
        }
        float w0 = W3[(size_t)k * HIDC + lane];
        float w1 = W3[(size_t)k * HIDC + lane + 32];
        float s3 = w0 * as3[lane] + w1 * as3[lane + 32];
        float d3 = w0 * ad3[lane] + w1 * ad3[lane + 32];
#pragma unroll
        for (int o = 16; o; o >>= 1) {
            s3 += __shfl_xor_sync(0xffffffffu, s3, o);
            d3 += __shfl_xor_sync(0xffffffffu, d3, o);
        }
        if (!lane) {
            int p = waperm(k);
            d_wa2s[p] = s; d_wa2d[p] = d;
            d_wa3s[p] = s3; d_wa3d[p] = d3;
        }
    }
}

// ================= zero: deg/cur/pool/cnt =================
__global__ void zero_all(int n) {
    int i = blockIdx.x * blockDim.x + threadIdx.x;
    if (i < n) { d_deg[i] = 0; d_cur[i] = 0; }
    if (i < GG * HIDC) d_pool[i] = 0.f;
    if (i < GG) d_cnt[i] = 0.f;
}

// ================= CSR construction =================
__global__ void hist_k(const int* __restrict__ ei, int E, int n) {
    int e = blockIdx.x * blockDim.x + threadIdx.x;
    int Etot = E + n;
    if (e >= Etot) return;
    int d = (e < E) ? __ldg(&ei[E + e]) : (e - E);
    atomicAdd(&d_deg[d], 1);
}

__global__ void scan_blk(int n) {
    int i = blockIdx.x * 1024 + threadIdx.x;
    int lane = threadIdx.x & 31, wid = threadIdx.x >> 5;
    int v = (i < n) ? d_deg[i] : 0;
    int x = v;
#pragma unroll
    for (int o = 1; o < 32; o <<= 1) {
        int t = __shfl_up_sync(0xffffffffu, x, o);
        if (lane >= o) x += t;
    }
    __shared__ int ws[32];
    if (lane == 31) ws[wid] = x;
    __syncthreads();
    if (wid == 0) {
        int y = ws[lane];
#pragma unroll
        for (int o = 1; o < 32; o <<= 1) {
            int t = __shfl_up_sync(0xffffffffu, y, o);
            if (lane >= o) y += t;
        }
        ws[lane] = y;
    }
    __syncthreads();
    int incl = x + (wid ? ws[wid - 1] : 0);
    if (i < n) d_off[i] = incl - v;
    if (threadIdx.x == 1023) d_bsum[blockIdx.x] = incl;
}

__global__ void scan_top(int nb) {
    int tid = threadIdx.x;
    int lane = tid & 31, wid = tid >> 5;
    int v = (tid < nb) ? d_bsum[tid] : 0;
    int x = v;
#pragma unroll
    for (int o = 1; o < 32; o <<= 1) {
        int t = __shfl_up_sync(0xffffffffu, x, o);
        if (lane >= o) x += t;
    }
    __shared__ int w0;
    if (wid == 0 && lane == 31) w0 = x;
    __syncthreads();
    int incl = x + (wid ? w0 : 0);
    if (tid < nb) d_bsum[tid] = incl - v;
}

__global__ void scan_add(int n) {
    int i = blockIdx.x * 1024 + threadIdx.x;
    if (i < n) d_off[i] += d_bsum[blockIdx.x];
}

__global__ void scatter_k(const int* __restrict__ ei, int E, int n) {
    int e = blockIdx.x * blockDim.x + threadIdx.x;
    int Etot = E + n;
    if (e >= Etot) return;
    int s, d;
    if (e < E) { s = __ldg(&ei[e]); d = __ldg(&ei[E + e]); } else { s = d = e - E; }
    int pos = d_off[d] + atomicAdd(&d_cur[d], 1);
    d_csr_src[pos] = s;
}

// ================= layer-1 attention coefficients =================
__global__ void gemv_attn(const float* __restrict__ x, int n) {
    __shared__ float4 ws[INC], wd[INC];
    for (int i = threadIdx.x; i < INC; i += 256) { ws[i] = d_wa1s[i]; wd[i] = d_wa1d[i]; }
    __syncthreads();
    int warp = (blockIdx.x * blockDim.x + threadIdx.x) >> 5;
    int lane = threadIdx.x & 31;
    if (warp >= n) return;
    float4 xv = *reinterpret_cast<const float4*>(&x[(size_t)warp * INC + lane * 4]);
    float xr[4] = {xv.x, xv.y, xv.z, xv.w};
    float ps[NHEADS] = {}, pd[NHEADS] = {};
#pragma unroll
    for (int j = 0; j < 4; j++) {
        float4 a = ws[j * 32 + lane];
        float4 b = wd[j * 32 + lane];
        ps[0] = fmaf(xr[j], a.x, ps[0]); ps[1] = fmaf(xr[j], a.y, ps[1]);
        ps[2] = fmaf(xr[j], a.z, ps[2]); ps[3] = fmaf(xr[j], a.w, ps[3]);
        pd[0] = fmaf(xr[j], b.x, pd[0]); pd[1] = fmaf(xr[j], b.y, pd[1]);
        pd[2] = fmaf(xr[j], b.z, pd[2]); pd[3] = fmaf(xr[j], b.w, pd[3]);
    }
#pragma unroll
    for (int h = 0; h < NHEADS; h++) {
#pragma unroll
        for (int o = 16; o; o >>= 1) {
            ps[h] += __shfl_xor_sync(0xffffffffu, ps[h], o);
            pd[h] += __shfl_xor_sync(0xffffffffu, pd[h], o);
        }
    }
    if (!lane) {
#pragma unroll
        for (int h = 0; h < NHEADS; h++) {
            d_asrcA[warp * NHEADS + h] = ps[h];
            d_adstA[warp * NHEADS + h] = pd[h];
        }
    }
}

// ================= TF32 GEMM (R6 version: cp.async double buffer, cvt at frag load) =================
__device__ __forceinline__ uint32_t cvt_tf32(float x) {
    uint32_t u;
    asm("cvt.rna.tf32.f32 %0, %1;" : "=r"(u) : "f"(x));
    return u;
}

__device__ __forceinline__ void mma_tf32(float c[4], uint32_t a0, uint32_t a1,
                                         uint32_t a2, uint32_t a3,
                                         uint32_t b0, uint32_t b1) {
    asm volatile(
        "mma.sync.aligned.m16n8k8.row.col.f32.tf32.tf32.f32 "
        "{%0,%1,%2,%3}, {%4,%5,%6,%7}, {%8,%9}, {%0,%1,%2,%3};"
        : "+f"(c[0]), "+f"(c[1]), "+f"(c[2]), "+f"(c[3])
        : "r"(a0), "r"(a1), "r"(a2), "r"(a3), "r"(b0), "r"(b1));
}

__device__ __forceinline__ void cp16p(float* smem_dst, const float* gsrc, bool pred) {
    unsigned sa = (unsigned)__cvta_generic_to_shared(smem_dst);
    int sz = pred ? 16 : 0;
    asm volatile("cp.async.ca.shared.global [%0], [%1], 16, %2;\n" :: "r"(sa), "l"(gsrc), "r"(sz));
}
__device__ __forceinline__ void cp_commit() { asm volatile("cp.async.commit_group;"); }
template <int N>
__device__ __forceinline__ void cp_wait() { asm volatile("cp.async.wait_group %0;" :: "n"(N)); }

template <int K, int NOUT, bool AG, int BN, int WM, int WN>
__launch_bounds__(256, 2)
__global__ void tgemm_k(const float* __restrict__ Ain, const float* __restrict__ B, int M) {
    constexpr int BM = 128, BK = 16;
    constexpr int MT = BM / (WM * 16);
    constexpr int NT = BN / (WN * 8);
    __shared__ float As[2][BM][BK + 4];
    __shared__ float Bs[2][BK][BN + 8];
    const float* A = AG ? (const float*)d_feat : Ain;

    int tid = threadIdx.x;
    int wid = tid >> 5, lane = tid & 31;
    int wm = wid % WM, wn = wid / WM;
    int row0 = blockIdx.y * BM;
    int col0 = blockIdx.x * BN;
    int lr = lane >> 2, lc = lane & 3;

    float c[MT][NT][4];
#pragma unroll
    for (int i = 0; i < MT; i++)
#pragma unroll
        for (int j = 0; j < NT; j++)
#pragma unroll
            for (int q = 0; q < 4; q++) c[i][j][q] = 0.f;

    constexpr int B4 = BN / 4;
    constexpr int BLD = (BK * B4) / 256;
    const int nk = K / BK;

    {
#pragma unroll
        for (int j = 0; j < 2; j++) {
            int idx = tid + j * 256;
            int r = idx >> 2, q = idx & 3;
            cp16p(&As[0][r][q * 4], &A[(size_t)(row0 + r) * K + q * 4], (row0 + r) < M);
        }
#pragma unroll
        for (int j = 0; j < BLD; j++) {
            int idx = tid + j * 256;
            int r = idx / B4, q = idx % B4;
            cp16p(&Bs[0][r][q * 4], &B[(size_t)r * NOUT + col0 + q * 4], true);
        }
        cp_commit();
    }

    for (int t = 0; t < nk; t++) {
        int cur = t & 1;
        if (t + 1 < nk) {
            int k0 = (t + 1) * BK;
#pragma unroll
            for (int j = 0; j < 2; j++) {
                int idx = tid + j * 256;
                int r = idx >> 2, q = idx & 3;
                cp16p(&As[1 - cur][r][q * 4], &A[(size_t)(row0 + r) * K + k0 + q * 4], (row0 + r) < M);
            }
#pragma unroll
            for (int j = 0; j < BLD; j++) {
                int idx = tid + j * 256;
                int r = idx / B4, q = idx % B4;
                cp16p(&Bs[1 - cur][r][q * 4], &B[(size_t)(k0 + r) * NOUT + col0 + q * 4], true);
            }
            cp_commit();
            cp_wait<1>();
        } else {
            cp_wait<0>();
        }
        __syncthreads();

#pragma unroll
        for (int kk = 0; kk < BK; kk += 8) {
            uint32_t af[MT][4], bf[NT][2];
#pragma unroll
            for (int mt = 0; mt < MT; mt++) {
                int bm = wm * MT * 16 + mt * 16;
                af[mt][0] = cvt_tf32(As[cur][bm + lr][kk + lc]);
                af[mt][1] = cvt_tf32(As[cur][bm + lr + 8][kk + lc]);
                af[mt][2] = cvt_tf32(As[cur][bm + lr][kk + lc + 4]);
                af[mt][3] = cvt_tf32(As[cur][bm + lr + 8][kk + lc + 4]);
            }
#pragma unroll
            for (int nt = 0; nt < NT; nt++) {
                int bn = wn * NT * 8 + nt * 8;
                bf[nt][0] = cvt_tf32(Bs[cur][kk + lc][bn + lr]);
                bf[nt][1] = cvt_tf32(Bs[cur][kk + lc + 4][bn + lr]);
            }
#pragma unroll
            for (int mt = 0; mt < MT; mt++)
#pragma unroll
                for (int nt = 0; nt < NT; nt++)
                    mma_tf32(c[mt][nt], af[mt][0], af[mt][1], af[mt][2], af[mt][3],
                             bf[nt][0], bf[nt][1]);
        }
        __syncthreads();
    }

#pragma unroll
    for (int mt = 0; mt < MT; mt++) {
        int r0 = row0 + wm * MT * 16 + mt * 16 + lr;
#pragma unroll
        for (int nt = 0; nt < NT; nt++) {
            int cc = col0 + wn * NT * 8 + nt * 8 + 2 * lc;
            if (r0 < M)
                *reinterpret_cast<float2*>(&d_h[(size_t)r0 * NOUT + cc]) =
                    make_float2(c[mt][nt][0], c[mt][nt][1]);
            if (r0 + 8 < M)
                *reinterpret_cast<float2*>(&d_h[(size_t)(r0 + 8) * NOUT + cc]) =
                    make_float2(c[mt][nt][2], c[mt][nt][3]);
        }
    }
}

// ================= fused aggregation: WPN warps per dst node =================
// H=4: WPN=2, each warp owns 128 channels (2 heads); H=1: WPN=1.
template <int H, int WPN, int HN, bool DOELU, bool SRCA, bool POOL>
__launch_bounds__(256)
__global__ void agg_k(const float* __restrict__ bias, const int* __restrict__ batch, int n) {
    constexpr int C = 64, F = H * C, CH = F / WPN, RF = CH / 32;  // RF: 4 (H=4) or 2 (H=1)
    constexpr int HL = (H == 4) ? 2 : 1;                          // heads owned per warp
    __shared__ float4 wsn4[HN == 4 ? F : 1], wdn4[HN == 4 ? F : 1];
    __shared__ float  wsn1[HN == 1 ? F : 1], wdn1[HN == 1 ? F : 1];
    __shared__ float  parts[8][8];
    if (HN == 4) {
        for (int i = threadIdx.x; i < F; i += 256) { wsn4[i] = d_wa2s[i]; wdn4[i] = d_wa2d[i]; }
        __syncthreads();
    } else if (HN == 1) {
        for (int i = threadIdx.x; i < F; i += 256) { wsn1[i] = d_wa3s[i]; wdn1[i] = d_wa3d[i]; }
        __syncthreads();
    }
    const float* asrc  = SRCA ? d_asrcA : d_asrcB;
    const float* adstp = SRCA ? d_adstA : d_adstB;
    float* nsrc = SRCA ? d_asrcB : d_asrcA;
    float* ndst = SRCA ? d_adstB : d_adstA;

    int gw   = (blockIdx.x * blockDim.x + threadIdx.x) >> 5;
    int wblk = threadIdx.x >> 5;
    int lane = threadIdx.x & 31;
    int node = gw / WPN;
    int sub  = gw % WPN;
    bool valid = node < n;

    float acc[RF];
#pragma unroll
    for (int k = 0; k < RF; k++) acc[k] = 0.f;

    if (valid) {
        int off = d_off[node], deg = d_deg[node];

        float ad[HL];
#pragma unroll
        for (int h = 0; h < HL; h++) ad[h] = adstp[node * H + sub * HL + h];

        // online softmax over incoming edges (only owned heads)
        float mx[HL], sv[HL];
#pragma unroll
        for (int h = 0; h < HL; h++) { mx[h] = -FLTMAX; sv[h] = 0.f; }
        for (int j = lane; j < deg; j += 32) {
            int s = d_csr_src[off + j];
            float av[HL];
            if (H == 4) {
                float2 a2 = *reinterpret_cast<const float2*>(&asrc[s * 4 + sub * 2]);
                av[0] = a2.x; av[1] = a2.y;
            } else {
                av[0] = asrc[s];
            }
#pragma unroll
            for (int h = 0; h < HL; h++) {
                float v = av[h] + ad[h];
                v = v > 0.f ? v : NEG * v;
                float nm = fmaxf(mx[h], v);
                sv[h] = sv[h] * __expf(mx[h] - nm) + __expf(v - nm);
                mx[h] = nm;
            }
        }
#pragma unroll
        for (int h = 0; h < HL; h++) {
#pragma unroll
            for (int o = 16; o; o >>= 1) {
                float om = __shfl_xor_sync(0xffffffffu, mx[h], o);
                float os = __shfl_xor_sync(0xffffffffu, sv[h], o);
                float nm = fmaxf(mx[h], om);
                sv[h] = sv[h] * __expf(mx[h] - nm) + os * __expf(om - nm);
                mx[h] = nm;
            }
            sv[h] = 1.f / (sv[h] + EPSV);
        }

        // weighted aggregation; lane covers RF contiguous channels of its sub-slice
        const int hl = (H == 4) ? (lane >> 4) : 0;   // local head: RF=4 -> 64ch per 16 lanes
        const float adh = ad[hl], mxh = mx[hl], svh = sv[hl];
        const int asoff = (H == 4) ? (sub * 2 + hl) : 0;

#pragma unroll 2
        for (int j = 0; j < deg; j++) {
            int s = d_csr_src[off + j];
            float v = asrc[s * H + asoff] + adh;
            v = v > 0.f ? v : NEG * v;
            float w = __expf(v - mxh) * svh;
            const float* hs = &d_h[(size_t)s * F + sub * CH + lane * RF];
            if (RF == 4) {
                float4 v0 = *reinterpret_cast<const float4*>(hs);
                acc[0] = fmaf(w, v0.x, acc[0]); acc[1] = fmaf(w, v0.y, acc[1]);
                acc[2] = fmaf(w, v0.z, acc[2]); acc[3] = fmaf(w, v0.w, acc[3]);
            } else {
                float2 v0 = *reinterpret_cast<const float2*>(hs);
                acc[0] = fmaf(w, v0.x, acc[0]); acc[1] = fmaf(w, v0.y, acc[1]);
            }
        }

        // bias + optional ELU
#pragma unroll
        for (int k = 0; k < RF; k++) {
            float v = acc[k] + bias[sub * CH + lane * RF + k];
            if (DOELU) v = v > 0.f ? v : (__expf(v) - 1.f);
            acc[k] = v;
        }

        if (POOL) {
            int g = __ldg(&batch[node]);
            atomicAdd(&d_pool[g * HIDC + lane * RF + 0], acc[0]);
            atomicAdd(&d_pool[g * HIDC + lane * RF + 1], acc[1]);
            if (!lane) atomicAdd(&d_cnt[g], 1.0f);
        } else {
            float* outp = &d_feat[(size_t)node * F + sub * CH + lane * RF];
            if (RF == 4)
                *reinterpret_cast<float4*>(outp) = make_float4(acc[0], acc[1], acc[2], acc[3]);
            else
                *reinterpret_cast<float2*>(outp) = make_float2(acc[0], acc[1]);
        }

        // partial next-layer coefficients over this warp's channels
        if (HN == 4) {
            float ps[4] = {}, pd[4] = {};
#pragma unroll
            for (int k = 0; k < RF; k++) {
                float4 a = wsn4[sub * CH + k * 32 + lane];
                float4 b = wdn4[sub * CH + k * 32 + lane];
                ps[0] = fmaf(acc[k], a.x, ps[0]); ps[1] = fmaf(acc[k], a.y, ps[1]);
                ps[2] = fmaf(acc[k], a.z, ps[2]); ps[3] = fmaf(acc[k], a.w, ps[3]);
                pd[0] = fmaf(acc[k], b.x, pd[0]); pd[1] = fmaf(acc[k], b.y, pd[1]);
                pd[2] = fmaf(acc[k], b.z, pd[2]); pd[3] = fmaf(acc[k], b.w, pd[3]);
            }
#pragma unroll
            for (int h = 0; h < 4; h++) {
#pragma unroll
                for (int o = 16; o; o >>= 1) {
                    ps[h] += __shfl_xor_sync(0xffffffffu, ps[h], o);
                    pd[h] += __shfl_xor_sync(0xffffffffu, pd[h], o);
                }
            }
            if (!lane) {
#pragma unroll
                for (int h = 0; h < 4; h++) {
                    parts[wblk][h] = ps[h];
                    parts[wblk][4 + h] = pd[h];
                }
            }
        } else if (HN == 1) {
            float ps = 0.f, pd = 0.f;
#pragma unroll
            for (int k = 0; k < RF; k++) {
                ps = fmaf(acc[k], wsn1[sub * CH + k * 32 + lane], ps);
                pd = fmaf(acc[k], wdn1[sub * CH + k * 32 + lane], pd);
            }
#pragma unroll
            for (int o = 16; o; o >>= 1) {
                ps += __shfl_xor_sync(0xffffffffu, ps, o);
                pd += __shfl_xor_sync(0xffffffffu, pd, o);
            }
            if (!lane) { parts[wblk][0] = ps; parts[wblk][1] = pd; }
        }
    }

    // cross-sub combine (WPN=2 pairs are adjacent warps in the same block)
    if (HN > 0) {
        __syncthreads();
        if (valid && sub == 0 && !lane) {
            if (HN == 4) {
#pragma unroll
                for (int h = 0; h < 4; h++) {
                    nsrc[node * 4 + h] = parts[wblk][h]     + parts[wblk + 1][h];
                    ndst[node * 4 + h] = parts[wblk][4 + h] + parts[wblk + 1][4 + h];
                }
            } else {
                nsrc[node] = parts[wblk][0] + parts[wblk + 1][0];
                ndst[node] = parts[wblk][1] + parts[wblk + 1][1];
            }
        }
    }
}

// ---------------- head ----------------
__global__ void head_k(const float* __restrict__ Wc, const float* __restrict__ bc,
                       float* __restrict__ out) {
    int t = blockIdx.x * blockDim.x + threadIdx.x;
    if (t >= GG * OUTC) return;
    int g = t / OUTC, o = t % OUTC;
    float inv = 1.f / fmaxf(d_cnt[g], 1.f);
    float s = 0.f;
#pragma unroll
    for (int c = 0; c < HIDC; c++) s += d_pool[g * HIDC + c] * Wc[c * OUTC + o];
    out[t] = s * inv + bc[o];
}

// ---------------- host orchestration ----------------
extern "C" void kernel_launch(void* const* d_in, const int* in_sizes, int n_in,
                              void* d_out, int out_size) {
    const float* x   = (const float*)d_in[0];
    const int*   ei  = (const int*)d_in[1];
    const int*   bat = (const int*)d_in[2];
    const float* W1 = (const float*)d_in[3],  *as1 = (const float*)d_in[4],
               * ad1 = (const float*)d_in[5], *b1  = (const float*)d_in[6];
    const float* W2 = (const float*)d_in[7],  *as2 = (const float*)d_in[8],
               * ad2 = (const float*)d_in[9], *b2  = (const float*)d_in[10];
    const float* W3 = (const float*)d_in[11], *as3 = (const float*)d_in[12],
               * ad3 = (const float*)d_in[13],*b3  = (const float*)d_in[14];
    const float* Wc = (const float*)d_in[15], *bc  = (const float*)d_in[16];
    float* out = (float*)d_out;

    int n    = in_sizes[0] / INC;
    int E    = in_sizes[1] / 2;
    int Etot = E + n;

    int gemm_rows = (n + 127) / 128;
    int eb    = (Etot + 255) / 256;
    int nb    = (n + 255) / 256;
    int sb    = (n + 1023) / 1024;
    int aggb2 = ((long long)n * 2 * 32 + 255) / 256;   // 2 warps per node
    int aggb1 = ((long long)n * 32 + 255) / 256;       // 1 warp per node

    // launch index 3 gets ncu-profiled -> layer-1 GEMM there
    wa_prep<<<32, 256>>>(W1, as1, ad1, W2, as2, ad2, W3, as3, ad3);         // 0
    zero_all<<<nb, 256>>>(n);                                               // 1
    hist_k<<<eb, 256>>>(ei, E, n);                                          // 2
    tgemm_k<INC, F1, false, 128, 2, 4><<<dim3(F1 / 128, gemm_rows), 256>>>(x, W1, n); // 3
    scan_blk<<<sb, 1024>>>(n);                                              // 4
    scan_top<<<1, 64>>>(sb);                                                // 5
    scan_add<<<sb, 1024>>>(n);                                              // 6
    scatter_k<<<eb, 256>>>(ei, E, n);                                       // 7
    gemv_attn<<<(n + 7) / 8, 256>>>(x, n);                                  // 8

    // ---- Layer 1 agg (H=4, 2 warps/node); writes layer-2 coeffs ----
    agg_k<NHEADS, 2, NHEADS, true, true, false><<<aggb2, 256>>>(b1, nullptr, n);

    // ---- Layer 2 (H=4, in=256, out=256) ----
    tgemm_k<F1, F1, true, 128, 2, 4><<<dim3(F1 / 128, gemm_rows), 256>>>(nullptr, W2, n);
    agg_k<NHEADS, 2, 1, true, false, false><<<aggb2, 256>>>(b2, nullptr, n);

    // ---- Layer 3 (H=1, in=256, out=64) ----
    tgemm_k<F1, HIDC, true, 64, 4, 2><<<dim3(1, gemm_rows), 256>>>(nullptr, W3, n);
    agg_k<1, 1, 0, false, true, true><<<aggb1, 256>>>(b3, bat, n);

    // ---- head ----
    head_k<<<(GG * OUTC + 255) / 256, 256>>>(Wc, bc, out);
}